// round 16
// baseline (speedup 1.0000x reference)
#include <cuda_runtime.h>
#include <cuda_fp16.h>
#include <stdint.h>

#define B_    4096
#define T_    256
#define D_    64
#define H_    256
#define NBLK  128
#define MTILE 32
#define NTHR  512

#define S_H 264   // fp32 h row stride (floats); 264 % 32 == 8 -> conflict-free

// Single continuous per-warp weight stream in exact consumption order:
//   tiles 0-11  : Wih1 (2 chunks)   [L1 x-part]
//   tiles 12-59 : Whh1 (8 chunks)   [L1 h-part]
//   tiles 60-107: Wih2 (8 chunks)   [L2 x-part, A = new h1]
//   tiles 108-155: Whh2 (8 chunks)  [L2 h-part]
//   tiles 156-161: replica of tiles 0-5 (ring tail -> next step's first chunk)
// Layout: [w16][tile 0..161][lane32] uint4 (lane's n8 x k32 B-frag half-pair)
#define NTILE 162
__device__ __align__(16) uint4 g_bW[16 * NTILE * 32 + 32];
__device__ __align__(16) uint4 g_bF [8 * 8 * 32 + 512];   // head: 8 warps

__device__ __forceinline__ uint32_t pkh(float a, float b) {
    __half2 h = __floats2half2_rn(a, b);
    return *reinterpret_cast<uint32_t*>(&h);
}
__device__ __forceinline__ void mma16(float* d, const uint32_t* a,
                                      uint32_t b0, uint32_t b1) {
    asm volatile(
        "mma.sync.aligned.m16n8k16.row.col.f32.f16.f16.f32 "
        "{%0,%1,%2,%3}, {%4,%5,%6,%7}, {%8,%9}, {%0,%1,%2,%3};\n"
        : "+f"(d[0]), "+f"(d[1]), "+f"(d[2]), "+f"(d[3])
        : "r"(a[0]), "r"(a[1]), "r"(a[2]), "r"(a[3]), "r"(b0), "r"(b1));
}
__device__ __forceinline__ void ldsm4(uint32_t* r, uint32_t addr) {
    asm volatile("ldmatrix.sync.aligned.m8n8.x4.shared.b16 {%0,%1,%2,%3}, [%4];"
                 : "=r"(r[0]), "=r"(r[1]), "=r"(r[2]), "=r"(r[3]) : "r"(addr));
}
__device__ __forceinline__ float ftanh(float x) {
    float y; asm("tanh.approx.f32 %0, %1;" : "=f"(y) : "f"(x)); return y;
}
__device__ __forceinline__ float fsig(float x) {
    return fmaf(0.5f, ftanh(0.5f * x), 0.5f);
}
__device__ __forceinline__ uint32_t cvta_s(const void* p) {
    return (uint32_t)__cvta_generic_to_shared(p);
}

// ---------------------------------------------------------------------------
// Repack the continuous stream (with tail replica).
__global__ void repack_w(const float* __restrict__ Wih1,
                         const float* __restrict__ Whh1,
                         const float* __restrict__ Wih2,
                         const float* __restrict__ Whh2) {
    int total = 16 * NTILE * 32;
    for (int o = blockIdx.x * blockDim.x + threadIdx.x; o < total;
         o += gridDim.x * blockDim.x) {
        int lane = o & 31, s = o >> 5;
        int tile = s % NTILE, w = s / NTILE;
        int i = (tile < 156) ? tile : tile - 156;   // replica maps to tile 0-5
        int q = i / 6, t = i % 6;
        int G = t >> 1, jt = t & 1, g = lane >> 2, tig = lane & 3;
        int n = G * H_ + w * 16 + jt * 8 + g;
        const float* W; int K, c2;
        if (q < 2)       { W = Wih1; K = 64;  c2 = q; }
        else if (q < 10) { W = Whh1; K = 256; c2 = q - 2; }
        else if (q < 18) { W = Wih2; K = 256; c2 = q - 10; }
        else             { W = Whh2; K = 256; c2 = q - 18; }
        const float* src = W + (size_t)n * K + c2 * 32 + 2 * tig;
        uint4 v;
        v.x = pkh(src[0],  src[1]);
        v.y = pkh(src[8],  src[9]);
        v.z = pkh(src[16], src[17]);
        v.w = pkh(src[24], src[25]);
        g_bW[o] = v;
    }
}
__global__ void repack_head(const float* __restrict__ W) {
    uint4* blob = g_bF;
    int total = 8 * 8 * 32;
    for (int o = blockIdx.x * blockDim.x + threadIdx.x; o < total;
         o += gridDim.x * blockDim.x) {
        int lane = o & 31, s = o >> 5;
        int c2 = s & 7, w = s >> 3;
        int g = lane >> 2, tig = lane & 3;
        int n = w * 8 + g;
        const float* src = W + (size_t)n * 256 + c2 * 32 + 2 * tig;
        uint4 v;
        v.x = pkh(src[0],  src[1]);
        v.y = pkh(src[8],  src[9]);
        v.z = pkh(src[16], src[17]);
        v.w = pkh(src[24], src[25]);
        blob[o] = v;
    }
}

// ---------------------------------------------------------------------------
// fp16 A tiles in smem: row r (0..31), 16B chunk c stored at chunk (c ^ (r&7)).
// One K-segment; A-frags via ldmatrix, weight ring depth 6 (one chunk),
// refills continue the global stream (ring passed in warm, left warm).
template <int NC2>
__device__ __forceinline__ void gemm_part(uint32_t aad0, uint32_t aad1,
                                          int lhi, int sxr,
                                          const uint4*& pf, uint4 (&buf)[6],
                                          float (&aR)[2][2][4],
                                          float (&aZ)[2][2][4],
                                          float (&aN)[2][2][4]) {
#pragma unroll 1
    for (int c2 = 0; c2 < NC2; c2++) {
        uint32_t af[2][2][4];
#pragma unroll
        for (int m = 0; m < 2; m++)
#pragma unroll
            for (int ch = 0; ch < 2; ch++) {
                int cc = c2 * 4 + ch * 2 + lhi;
                uint32_t addr = (m ? aad1 : aad0) + (uint32_t)((cc ^ sxr) << 4);
                ldsm4(af[m][ch], addr);
            }
#pragma unroll
        for (int t = 0; t < 6; t++) {
            uint4 wv = buf[t];
            buf[t] = *pf;  pf += 32;       // prefetch distance = 6 (next chunk)
            float (*acc)[2][4] = (t < 2) ? aR : (t < 4) ? aZ : aN;
            int jt = t & 1;
            mma16(acc[jt][0], af[0][0], wv.x, wv.y);
            mma16(acc[jt][1], af[1][0], wv.x, wv.y);
            mma16(acc[jt][0], af[0][1], wv.z, wv.w);
            mma16(acc[jt][1], af[1][1], wv.z, wv.w);
        }
    }
}

// Full layer GEMM: x-part (CX chunks) then h-part (8 chunks); the ring stays
// warm across calls (no internal warmup).
template <int CX>
__device__ __forceinline__ void gemmL(uint32_t ax, uint32_t ah, int rbx_shift,
                                      const uint4*& pf, uint4 (&buf)[6],
                                      int lhi, int sxr,
                                      float (&aR)[2][2][4], float (&aZ)[2][2][4],
                                      float (&aNi)[2][2][4],
                                      float (&aNh)[2][2][4]) {
    gemm_part<CX>(ax, ax + (16u << rbx_shift), lhi, sxr, pf, buf, aR, aZ, aNi);
    gemm_part<8>(ah, ah + 16 * 512, lhi, sxr, pf, buf, aR, aZ, aNh);
}

// Head GEMM (warps 0-7 only): n8 tile per warp, K=256.
__device__ __forceinline__ void gemmH(uint32_t ah,
                                      const uint4* __restrict__ blobWL,
                                      int lhi, int sxr, float (&acc)[2][4]) {
    uint4 buf[8];
#pragma unroll
    for (int i = 0; i < 8; i++) buf[i] = blobWL[i * 32];
#pragma unroll 1
    for (int c2 = 0; c2 < 8; c2++) {
        uint32_t af[2][2][4];
#pragma unroll
        for (int m = 0; m < 2; m++)
#pragma unroll
            for (int ch = 0; ch < 2; ch++) {
                int cc = c2 * 4 + ch * 2 + lhi;
                uint32_t addr = (m ? ah + 16 * 512 : ah) +
                                (uint32_t)((cc ^ sxr) << 4);
                ldsm4(af[m][ch], addr);
            }
        uint4 wv = buf[c2];
        mma16(acc[0], af[0][0], wv.x, wv.y);
        mma16(acc[1], af[1][0], wv.x, wv.y);
        mma16(acc[0], af[0][1], wv.z, wv.w);
        mma16(acc[1], af[1][1], wv.z, wv.w);
    }
}

__device__ __forceinline__ void zero4(float (&aR)[2][2][4], float (&aZ)[2][2][4],
                                      float (&aNi)[2][2][4],
                                      float (&aNh)[2][2][4]) {
#pragma unroll
    for (int jt = 0; jt < 2; jt++)
#pragma unroll
        for (int m = 0; m < 2; m++)
#pragma unroll
            for (int q = 0; q < 4; q++) {
                aR[jt][m][q] = 0.f; aZ[jt][m][q] = 0.f;
                aNi[jt][m][q] = 0.f; aNh[jt][m][q] = 0.f;
            }
}

// GRU gate math + h update. Writes fp32 h' and swizzled fp16 h'.
__device__ __forceinline__ void epilogue(float (&aR)[2][2][4], float (&aZ)[2][2][4],
                                         float (&aNi)[2][2][4],
                                         float (&aNh)[2][2][4],
                                         const float* __restrict__ hc, float* hn,
                                         char* hn16,
                                         const float* __restrict__ sB,
                                         int w, int g, int tig) {
#pragma unroll
    for (int jt = 0; jt < 2; jt++) {
        int j0 = w * 16 + jt * 8 + 2 * tig;
        float br0 = sB[j0],          br1 = sB[j0 + 1];
        float bz0 = sB[H_ + j0],     bz1 = sB[H_ + j0 + 1];
        float bi0 = sB[2 * H_ + j0], bi1 = sB[2 * H_ + j0 + 1];
        float bh0 = sB[3 * H_ + j0], bh1 = sB[3 * H_ + j0 + 1];
        int cc = 2 * w + jt;   // 16B chunk of cols j0..j0+7
#pragma unroll
        for (int m = 0; m < 2; m++)
#pragma unroll
            for (int hq = 0; hq < 2; hq++) {
                int row = g + hq * 8 + m * 16;
                int q0 = hq * 2, q1 = hq * 2 + 1;
                int i0 = row * S_H + j0;
                float r0 = fsig(aR[jt][m][q0] + br0);
                float r1 = fsig(aR[jt][m][q1] + br1);
                float z0 = fsig(aZ[jt][m][q0] + bz0);
                float z1 = fsig(aZ[jt][m][q1] + bz1);
                float n0 = ftanh(aNi[jt][m][q0] + bi0 + r0 * (aNh[jt][m][q0] + bh0));
                float n1 = ftanh(aNi[jt][m][q1] + bi1 + r1 * (aNh[jt][m][q1] + bh1));
                float h0 = (1.f - z0) * n0 + z0 * hc[i0];
                float h1 = (1.f - z1) * n1 + z1 * hc[i0 + 1];
                float2 v; v.x = h0; v.y = h1;
                *reinterpret_cast<float2*>(hn + i0) = v;
                *reinterpret_cast<__half2*>(
                    hn16 + row * 512 + ((cc ^ (row & 7)) << 4) + tig * 4) =
                    __floats2half2_rn(h0, h1);
            }
    }
}

// ---------------------------------------------------------------------------
extern __shared__ float smem[];

__global__ void __launch_bounds__(NTHR, 1)
gru_main(const float* __restrict__ x, const float* __restrict__ h1g,
         const float* __restrict__ h2g,
         const float* __restrict__ bih1, const float* __restrict__ bhh1,
         const float* __restrict__ bih2, const float* __restrict__ bhh2,
         const float* __restrict__ bfc, float* __restrict__ out) {
    float* sh1 = smem;                      // fp32 h1: 2 buf x 32 x S_H
    float* sh2 = sh1 + 2 * MTILE * S_H;     // fp32 h2
    float* sB1 = sh2 + 2 * MTILE * S_H;     // 4*256
    float* sB2 = sB1 + 4 * H_;              // 4*256
    float* sBf = sB2 + 4 * H_;              // 64
    char*  h16_1 = (char*)(sBf + 64);       // fp16 h1: 2 buf x 32 x 512B
    char*  h16_2 = h16_1 + 2 * 32 * 512;    // fp16 h2
    char*  x16   = h16_2 + 2 * 32 * 512;    // fp16 x : 2 buf x 32 x 128B

    const int tid = threadIdx.x;
    const int w = tid >> 5, lane = tid & 31, g = lane >> 2, tig = lane & 3;
    const int l16 = lane & 15, lhi = lane >> 4, sxr = l16 & 7;
    const int b0 = blockIdx.x * MTILE;

    // combined biases into shared (threads 0..255)
    if (tid < 256) {
        sB1[tid]          = bih1[tid] + bhh1[tid];
        sB1[H_ + tid]     = bih1[H_ + tid] + bhh1[H_ + tid];
        sB1[2 * H_ + tid] = bih1[2 * H_ + tid];
        sB1[3 * H_ + tid] = bhh1[2 * H_ + tid];
        sB2[tid]          = bih2[tid] + bhh2[tid];
        sB2[H_ + tid]     = bih2[H_ + tid] + bhh2[H_ + tid];
        sB2[2 * H_ + tid] = bih2[2 * H_ + tid];
        sB2[3 * H_ + tid] = bhh2[2 * H_ + tid];
        if (tid < D_) sBf[tid] = bfc[tid];

        // init h buffer 0 (fp32 + swizzled fp16)
        int cc = tid >> 3, cb = tid & 7;
        for (int i = 0; i < MTILE; i++) {
            float v1 = h1g[(size_t)(b0 + i) * H_ + tid];
            float v2 = h2g[(size_t)(b0 + i) * H_ + tid];
            sh1[i * S_H + tid] = v1;
            sh2[i * S_H + tid] = v2;
            int off = i * 512 + ((cc ^ (i & 7)) << 4) + cb * 2;
            *reinterpret_cast<__half*>(h16_1 + off) = __float2half_rn(v1);
            *reinterpret_cast<__half*>(h16_2 + off) = __float2half_rn(v2);
        }
    }

    // x staging coords (threads 0..255)
    const int xr = (tid & 255) >> 3, xcc = tid & 7;
    const float* xbase = x + ((size_t)(b0 + xr) * T_) * D_ + xcc * 8;
    const int xoff = xr * 128 + ((xcc ^ (xr & 7)) << 4);

    if (tid < 256) {
        float4 v0 = *reinterpret_cast<const float4*>(xbase);
        float4 v1 = *reinterpret_cast<const float4*>(xbase + 4);
        uint4 p;
        p.x = pkh(v0.x, v0.y); p.y = pkh(v0.z, v0.w);
        p.z = pkh(v1.x, v1.y); p.w = pkh(v1.z, v1.w);
        *reinterpret_cast<uint4*>(x16 + xoff) = p;
    }

    // shared-space byte addresses for ldmatrix (lane row folded in)
    const uint32_t u16_1 = cvta_s(h16_1) + l16 * 512;
    const uint32_t u16_2 = cvta_s(h16_2) + l16 * 512;
    const uint32_t ux16  = cvta_s(x16) + l16 * 128;

    // per-warp stream bases (lane folded in)
    const uint4* pwbase = g_bW + (size_t)w * NTILE * 32 + lane;
    const uint4* bF     = g_bF + (size_t)(w & 7) * 8 * 32 + lane;

    // warm the persistent ring ONCE; it never goes cold again.
    const uint4* pf;
    uint4 buf[6];
#pragma unroll
    for (int i = 0; i < 6; i++) buf[i] = pwbase[i * 32];
    pf = pwbase + 6 * 32;

    float aR[2][2][4], aZ[2][2][4], aNi[2][2][4], aNh[2][2][4];

    for (int t = 0; t < T_; t++) {
        const int cur = t & 1;
        float* h1c = sh1 + cur * MTILE * S_H;
        float* h1n = sh1 + (cur ^ 1) * MTILE * S_H;
        float* h2c = sh2 + cur * MTILE * S_H;
        float* h2n = sh2 + (cur ^ 1) * MTILE * S_H;
        uint32_t a_h1c = u16_1 + cur * 16384;
        uint32_t a_h1n = u16_1 + (cur ^ 1) * 16384;
        uint32_t a_h2c = u16_2 + cur * 16384;
        uint32_t a_h2n = u16_2 + (cur ^ 1) * 16384;
        uint32_t a_x   = ux16 + cur * 4096;
        char* h1n16 = h16_1 + (cur ^ 1) * 16384;
        char* h2n16 = h16_2 + (cur ^ 1) * 16384;

        __syncthreads();   // x[cur] staged, previous-step writes visible

        // issue x_{t+1} loads early
        float4 vx0, vx1;
        if (tid < 256 && t + 1 < T_) {
            const float* xp = xbase + (size_t)(t + 1) * D_;
            vx0 = *reinterpret_cast<const float4*>(xp);
            vx1 = *reinterpret_cast<const float4*>(xp + 4);
        }

        // ---- Layer 1 (x-part + h-part, continuous stream) ----
        zero4(aR, aZ, aNi, aNh);
        gemmL<2>(a_x, a_h1c, 7, pf, buf, lhi, sxr, aR, aZ, aNi, aNh);
        epilogue(aR, aZ, aNi, aNh, h1c, h1n, h1n16, sB1, w, g, tig);
        __syncthreads();

        // ---- Layer 2 (input = new h1; stream continues) ----
        zero4(aR, aZ, aNi, aNh);
        gemmL<8>(a_h1n, a_h2c, 9, pf, buf, lhi, sxr, aR, aZ, aNi, aNh);
        epilogue(aR, aZ, aNi, aNh, h2c, h2n, h2n16, sB2, w, g, tig);
        __syncthreads();

        // ---- Head (warps 0-7): y_t = h2_new @ W_fc^T + b_fc ----
        if (w < 8) {
            float aF[2][4];
#pragma unroll
            for (int m = 0; m < 2; m++)
#pragma unroll
                for (int q = 0; q < 4; q++) aF[m][q] = 0.f;
            gemmH(a_h2n, bF, lhi, sxr, aF);
            int d0 = w * 8 + 2 * tig;
            float bs0 = sBf[d0], bs1 = sBf[d0 + 1];
#pragma unroll
            for (int m = 0; m < 2; m++) {
                int r0 = g + m * 16, r1 = g + 8 + m * 16;
                float2 v;
                v.x = aF[m][0] + bs0; v.y = aF[m][1] + bs1;
                *reinterpret_cast<float2*>(
                    out + ((size_t)(b0 + r0) * T_ + t) * D_ + d0) = v;
                v.x = aF[m][2] + bs0; v.y = aF[m][3] + bs1;
                *reinterpret_cast<float2*>(
                    out + ((size_t)(b0 + r1) * T_ + t) * D_ + d0) = v;
            }
        }

        // park x_{t+1} into the other fp16 x buffer
        if (tid < 256 && t + 1 < T_) {
            uint4 p;
            p.x = pkh(vx0.x, vx0.y); p.y = pkh(vx0.z, vx0.w);
            p.z = pkh(vx1.x, vx1.y); p.w = pkh(vx1.z, vx1.w);
            *reinterpret_cast<uint4*>(x16 + (cur ^ 1) * 4096 + xoff) = p;
        }

        // stream wrap: during the last chunk the refills read the tail
        // replica (== next step's first chunk), so buf is already warm;
        // just rewind the pointer. No branch inside the gemm loops.
        pf = pwbase + 6 * 32;
    }
    __syncthreads();

    // final states (t=255 wrote buffer 0)
    if (tid < 256) {
        size_t base = (size_t)B_ * T_ * D_;
        for (int i = 0; i < MTILE; i++) {
            out[base + (size_t)(b0 + i) * H_ + tid] = sh1[i * S_H + tid];
            out[base + (size_t)B_ * H_ + (size_t)(b0 + i) * H_ + tid] =
                sh2[i * S_H + tid];
        }
    }
}

// ---------------------------------------------------------------------------
extern "C" void kernel_launch(void* const* d_in, const int* in_sizes, int n_in,
                              void* d_out, int out_size) {
    (void)in_sizes; (void)n_in; (void)out_size;
    const float* x     = (const float*)d_in[0];
    const float* h1    = (const float*)d_in[1];
    const float* h2    = (const float*)d_in[2];
    const float* W_ih1 = (const float*)d_in[3];
    const float* W_hh1 = (const float*)d_in[4];
    const float* b_ih1 = (const float*)d_in[5];
    const float* b_hh1 = (const float*)d_in[6];
    const float* W_ih2 = (const float*)d_in[7];
    const float* W_hh2 = (const float*)d_in[8];
    const float* b_ih2 = (const float*)d_in[9];
    const float* b_hh2 = (const float*)d_in[10];
    const float* W_fc  = (const float*)d_in[11];
    const float* b_fc  = (const float*)d_in[12];
    float* out = (float*)d_out;

    repack_w<<<324, 256>>>(W_ih1, W_hh1, W_ih2, W_hh2);
    repack_head<<<8, 256>>>(W_fc);

    const int smem_bytes =
        (2 * MTILE * S_H * 2 + 4 * H_ * 2 + 64) * (int)sizeof(float) +
        2 * 32 * 512 * 2 +   // fp16 h1, h2 (double buffered)
        2 * 32 * 128;        // fp16 x (double buffered)
    cudaFuncSetAttribute(gru_main, cudaFuncAttributeMaxDynamicSharedMemorySize,
                         smem_bytes);

    gru_main<<<NBLK, NTHR, smem_bytes>>>(x, h1, h2, b_ih1, b_hh1, b_ih2, b_hh2,
                                         b_fc, out);
}

// round 17
// speedup vs baseline: 1.0894x; 1.0894x over previous
#include <cuda_runtime.h>
#include <cuda_fp16.h>
#include <stdint.h>

#define B_    4096
#define T_    256
#define D_    64
#define H_    256
#define NBLK  128
#define MTILE 32
#define NTHR  512

#define S_H 264   // fp32 h row stride (floats); 264 % 32 == 8 -> conflict-free

// Combined per-layer fp16 weight blobs, 16-warp layout:
//   blob[w16][c2][t=G*2+jt (6)][lane], uint4 = lane's B-frag for n8 x k32.
// Warp w owns gate cols [G*256 + w*16, +16) for each gate G.
__device__ __align__(16) uint4 g_bL1[16 * 10 * 6 * 32 + 512];
__device__ __align__(16) uint4 g_bL2[16 * 16 * 6 * 32 + 512];
__device__ __align__(16) uint4 g_bF [8 * 8 * 32 + 512];   // head: 8 warps

__device__ __forceinline__ uint32_t pkh(float a, float b) {
    __half2 h = __floats2half2_rn(a, b);
    return *reinterpret_cast<uint32_t*>(&h);
}
__device__ __forceinline__ void mma16(float* d, const uint32_t* a,
                                      uint32_t b0, uint32_t b1) {
    asm volatile(
        "mma.sync.aligned.m16n8k16.row.col.f32.f16.f16.f32 "
        "{%0,%1,%2,%3}, {%4,%5,%6,%7}, {%8,%9}, {%0,%1,%2,%3};\n"
        : "+f"(d[0]), "+f"(d[1]), "+f"(d[2]), "+f"(d[3])
        : "r"(a[0]), "r"(a[1]), "r"(a[2]), "r"(a[3]), "r"(b0), "r"(b1));
}
__device__ __forceinline__ void ldsm4(uint32_t* r, uint32_t addr) {
    asm volatile("ldmatrix.sync.aligned.m8n8.x4.shared.b16 {%0,%1,%2,%3}, [%4];"
                 : "=r"(r[0]), "=r"(r[1]), "=r"(r[2]), "=r"(r[3]) : "r"(addr));
}
__device__ __forceinline__ float ftanh(float x) {
    float y; asm("tanh.approx.f32 %0, %1;" : "=f"(y) : "f"(x)); return y;
}
__device__ __forceinline__ float fsig(float x) {
    return fmaf(0.5f, ftanh(0.5f * x), 0.5f);
}
__device__ __forceinline__ uint32_t cvta_s(const void* p) {
    return (uint32_t)__cvta_generic_to_shared(p);
}

// ---------------------------------------------------------------------------
// Repack combined layer blob: Wx[3H x Kx] then Wh[3H x 256], 16-warp layout.
__global__ void repack_comb(const float* __restrict__ Wx,
                            const float* __restrict__ Wh, int Kx, int id) {
    uint4* blob = (id == 0) ? g_bL1 : g_bL2;
    int CX = Kx >> 5;
    int NC = CX + 8;
    int total = 16 * NC * 6 * 32;
    for (int o = blockIdx.x * blockDim.x + threadIdx.x; o < total;
         o += gridDim.x * blockDim.x) {
        int lane = o & 31, s = o >> 5;
        int t = s % 6, c2 = (s / 6) % NC, w = s / (6 * NC);
        int G = t >> 1, jt = t & 1, g = lane >> 2, tig = lane & 3;
        int n = G * H_ + w * 16 + jt * 8 + g;
        const float* src = (c2 < CX)
            ? Wx + (size_t)n * Kx + c2 * 32 + 2 * tig
            : Wh + (size_t)n * 256 + (c2 - CX) * 32 + 2 * tig;
        uint4 v;
        v.x = pkh(src[0],  src[1]);
        v.y = pkh(src[8],  src[9]);
        v.z = pkh(src[16], src[17]);
        v.w = pkh(src[24], src[25]);
        blob[o] = v;
    }
}
__global__ void repack_head(const float* __restrict__ W) {
    uint4* blob = g_bF;
    int total = 8 * 8 * 32;
    for (int o = blockIdx.x * blockDim.x + threadIdx.x; o < total;
         o += gridDim.x * blockDim.x) {
        int lane = o & 31, s = o >> 5;
        int c2 = s & 7, w = s >> 3;
        int g = lane >> 2, tig = lane & 3;
        int n = w * 8 + g;
        const float* src = W + (size_t)n * 256 + c2 * 32 + 2 * tig;
        uint4 v;
        v.x = pkh(src[0],  src[1]);
        v.y = pkh(src[8],  src[9]);
        v.z = pkh(src[16], src[17]);
        v.w = pkh(src[24], src[25]);
        blob[o] = v;
    }
}

// ---------------------------------------------------------------------------
// fp16 A tiles in smem: row r (0..31), 16B chunk c stored at chunk (c ^ (r&7)).
// One K-segment; A-frags via ldmatrix, weight ring depth 6 (one chunk).
// TWO-PASS MMA ordering: pass 1 issues all 12 half-0 MMAs (12 distinct
// accumulators -> RAW distance 12), pass 2 all half-1 MMAs with ring refill.
// Per-accumulator contribution order (half-0 then half-1) is preserved, so
// numerics are bit-identical to the single-pass version.
template <int NC2>
__device__ __forceinline__ void gemm_part(uint32_t aad0, uint32_t aad1,
                                          int lhi, int sxr,
                                          const uint4*& pf, uint4 (&buf)[6],
                                          float (&aR)[2][2][4],
                                          float (&aZ)[2][2][4],
                                          float (&aN)[2][2][4]) {
#pragma unroll 1
    for (int c2 = 0; c2 < NC2; c2++) {
        uint32_t af[2][2][4];
#pragma unroll
        for (int m = 0; m < 2; m++)
#pragma unroll
            for (int ch = 0; ch < 2; ch++) {
                int cc = c2 * 4 + ch * 2 + lhi;
                uint32_t addr = (m ? aad1 : aad0) + (uint32_t)((cc ^ sxr) << 4);
                ldsm4(af[m][ch], addr);
            }
        // pass 1: k16 half-0, 12 distinct accumulators
#pragma unroll
        for (int t = 0; t < 6; t++) {
            float (*acc)[2][4] = (t < 2) ? aR : (t < 4) ? aZ : aN;
            int jt = t & 1;
            mma16(acc[jt][0], af[0][0], buf[t].x, buf[t].y);
            mma16(acc[jt][1], af[1][0], buf[t].x, buf[t].y);
        }
        // pass 2: k16 half-1 + ring refill (prefetch distance = 1 chunk)
#pragma unroll
        for (int t = 0; t < 6; t++) {
            uint32_t bz = buf[t].z, bw = buf[t].w;
            buf[t] = *pf;  pf += 32;
            float (*acc)[2][4] = (t < 2) ? aR : (t < 4) ? aZ : aN;
            int jt = t & 1;
            mma16(acc[jt][0], af[0][1], bz, bw);
            mma16(acc[jt][1], af[1][1], bz, bw);
        }
    }
}

// Full layer GEMM: x-part (CX chunks) then h-part (8 chunks), one continuous
// weight stream, single warm ring.
template <int CX>
__device__ __forceinline__ void gemmL(uint32_t ax, uint32_t ah, int rbx_shift,
                                      const uint4* __restrict__ blobWL,
                                      int lhi, int sxr,
                                      float (&aR)[2][2][4], float (&aZ)[2][2][4],
                                      float (&aNi)[2][2][4],
                                      float (&aNh)[2][2][4]) {
    const uint4* pf = blobWL;
    uint4 buf[6];
#pragma unroll
    for (int i = 0; i < 6; i++) buf[i] = pf[i * 32];
    pf += 6 * 32;
    gemm_part<CX>(ax, ax + (16u << rbx_shift), lhi, sxr, pf, buf, aR, aZ, aNi);
    gemm_part<8>(ah, ah + 16 * 512, lhi, sxr, pf, buf, aR, aZ, aNh);
}

// Head GEMM (warps 0-7 only): n8 tile per warp, K=256.
__device__ __forceinline__ void gemmH(uint32_t ah,
                                      const uint4* __restrict__ blobWL,
                                      int lhi, int sxr, float (&acc)[2][4]) {
    uint4 buf[8];
#pragma unroll
    for (int i = 0; i < 8; i++) buf[i] = blobWL[i * 32];
#pragma unroll 1
    for (int c2 = 0; c2 < 8; c2++) {
        uint32_t af[2][2][4];
#pragma unroll
        for (int m = 0; m < 2; m++)
#pragma unroll
            for (int ch = 0; ch < 2; ch++) {
                int cc = c2 * 4 + ch * 2 + lhi;
                uint32_t addr = (m ? ah + 16 * 512 : ah) +
                                (uint32_t)((cc ^ sxr) << 4);
                ldsm4(af[m][ch], addr);
            }
        uint4 wv = buf[c2];
        mma16(acc[0], af[0][0], wv.x, wv.y);
        mma16(acc[1], af[1][0], wv.x, wv.y);
        mma16(acc[0], af[0][1], wv.z, wv.w);
        mma16(acc[1], af[1][1], wv.z, wv.w);
    }
}

__device__ __forceinline__ void zero4(float (&aR)[2][2][4], float (&aZ)[2][2][4],
                                      float (&aNi)[2][2][4],
                                      float (&aNh)[2][2][4]) {
#pragma unroll
    for (int jt = 0; jt < 2; jt++)
#pragma unroll
        for (int m = 0; m < 2; m++)
#pragma unroll
            for (int q = 0; q < 4; q++) {
                aR[jt][m][q] = 0.f; aZ[jt][m][q] = 0.f;
                aNi[jt][m][q] = 0.f; aNh[jt][m][q] = 0.f;
            }
}

// GRU gate math + h update. Writes fp32 h' and swizzled fp16 h'.
__device__ __forceinline__ void epilogue(float (&aR)[2][2][4], float (&aZ)[2][2][4],
                                         float (&aNi)[2][2][4],
                                         float (&aNh)[2][2][4],
                                         const float* __restrict__ hc, float* hn,
                                         char* hn16,
                                         const float* __restrict__ sB,
                                         int w, int g, int tig) {
#pragma unroll
    for (int jt = 0; jt < 2; jt++) {
        int j0 = w * 16 + jt * 8 + 2 * tig;
        float br0 = sB[j0],          br1 = sB[j0 + 1];
        float bz0 = sB[H_ + j0],     bz1 = sB[H_ + j0 + 1];
        float bi0 = sB[2 * H_ + j0], bi1 = sB[2 * H_ + j0 + 1];
        float bh0 = sB[3 * H_ + j0], bh1 = sB[3 * H_ + j0 + 1];
        int cc = 2 * w + jt;   // 16B chunk of cols j0..j0+7
#pragma unroll
        for (int m = 0; m < 2; m++)
#pragma unroll
            for (int hq = 0; hq < 2; hq++) {
                int row = g + hq * 8 + m * 16;
                int q0 = hq * 2, q1 = hq * 2 + 1;
                int i0 = row * S_H + j0;
                float r0 = fsig(aR[jt][m][q0] + br0);
                float r1 = fsig(aR[jt][m][q1] + br1);
                float z0 = fsig(aZ[jt][m][q0] + bz0);
                float z1 = fsig(aZ[jt][m][q1] + bz1);
                float n0 = ftanh(aNi[jt][m][q0] + bi0 + r0 * (aNh[jt][m][q0] + bh0));
                float n1 = ftanh(aNi[jt][m][q1] + bi1 + r1 * (aNh[jt][m][q1] + bh1));
                float h0 = (1.f - z0) * n0 + z0 * hc[i0];
                float h1 = (1.f - z1) * n1 + z1 * hc[i0 + 1];
                float2 v; v.x = h0; v.y = h1;
                *reinterpret_cast<float2*>(hn + i0) = v;
                *reinterpret_cast<__half2*>(
                    hn16 + row * 512 + ((cc ^ (row & 7)) << 4) + tig * 4) =
                    __floats2half2_rn(h0, h1);
            }
    }
}

// ---------------------------------------------------------------------------
extern __shared__ float smem[];

__global__ void __launch_bounds__(NTHR, 1)
gru_main(const float* __restrict__ x, const float* __restrict__ h1g,
         const float* __restrict__ h2g,
         const float* __restrict__ bih1, const float* __restrict__ bhh1,
         const float* __restrict__ bih2, const float* __restrict__ bhh2,
         const float* __restrict__ bfc, float* __restrict__ out) {
    float* sh1 = smem;                      // fp32 h1: 2 buf x 32 x S_H
    float* sh2 = sh1 + 2 * MTILE * S_H;     // fp32 h2
    float* sB1 = sh2 + 2 * MTILE * S_H;     // 4*256
    float* sB2 = sB1 + 4 * H_;              // 4*256
    float* sBf = sB2 + 4 * H_;              // 64
    char*  h16_1 = (char*)(sBf + 64);       // fp16 h1: 2 buf x 32 x 512B
    char*  h16_2 = h16_1 + 2 * 32 * 512;    // fp16 h2
    char*  x16   = h16_2 + 2 * 32 * 512;    // fp16 x : 2 buf x 32 x 128B

    const int tid = threadIdx.x;
    const int w = tid >> 5, lane = tid & 31, g = lane >> 2, tig = lane & 3;
    const int l16 = lane & 15, lhi = lane >> 4, sxr = l16 & 7;
    const int b0 = blockIdx.x * MTILE;

    // combined biases into shared (threads 0..255)
    if (tid < 256) {
        sB1[tid]          = bih1[tid] + bhh1[tid];
        sB1[H_ + tid]     = bih1[H_ + tid] + bhh1[H_ + tid];
        sB1[2 * H_ + tid] = bih1[2 * H_ + tid];
        sB1[3 * H_ + tid] = bhh1[2 * H_ + tid];
        sB2[tid]          = bih2[tid] + bhh2[tid];
        sB2[H_ + tid]     = bih2[H_ + tid] + bhh2[H_ + tid];
        sB2[2 * H_ + tid] = bih2[2 * H_ + tid];
        sB2[3 * H_ + tid] = bhh2[2 * H_ + tid];
        if (tid < D_) sBf[tid] = bfc[tid];

        // init h buffer 0 (fp32 + swizzled fp16)
        int cc = tid >> 3, cb = tid & 7;
        for (int i = 0; i < MTILE; i++) {
            float v1 = h1g[(size_t)(b0 + i) * H_ + tid];
            float v2 = h2g[(size_t)(b0 + i) * H_ + tid];
            sh1[i * S_H + tid] = v1;
            sh2[i * S_H + tid] = v2;
            int off = i * 512 + ((cc ^ (i & 7)) << 4) + cb * 2;
            *reinterpret_cast<__half*>(h16_1 + off) = __float2half_rn(v1);
            *reinterpret_cast<__half*>(h16_2 + off) = __float2half_rn(v2);
        }
    }

    // x staging coords (threads 0..255)
    const int xr = (tid & 255) >> 3, xcc = tid & 7;
    const float* xbase = x + ((size_t)(b0 + xr) * T_) * D_ + xcc * 8;
    const int xoff = xr * 128 + ((xcc ^ (xr & 7)) << 4);

    if (tid < 256) {
        float4 v0 = *reinterpret_cast<const float4*>(xbase);
        float4 v1 = *reinterpret_cast<const float4*>(xbase + 4);
        uint4 p;
        p.x = pkh(v0.x, v0.y); p.y = pkh(v0.z, v0.w);
        p.z = pkh(v1.x, v1.y); p.w = pkh(v1.z, v1.w);
        *reinterpret_cast<uint4*>(x16 + xoff) = p;
    }

    // shared-space byte addresses for ldmatrix (lane row folded in)
    const uint32_t u16_1 = cvta_s(h16_1) + l16 * 512;
    const uint32_t u16_2 = cvta_s(h16_2) + l16 * 512;
    const uint32_t ux16  = cvta_s(x16) + l16 * 128;

    // per-warp blob bases (lane folded in)
    const uint4* bL1 = g_bL1 + (size_t)w * 10 * 6 * 32 + lane;
    const uint4* bL2 = g_bL2 + (size_t)w * 16 * 6 * 32 + lane;
    const uint4* bF  = g_bF  + (size_t)(w & 7) * 8 * 32 + lane;

    float aR[2][2][4], aZ[2][2][4], aNi[2][2][4], aNh[2][2][4];

    for (int t = 0; t < T_; t++) {
        const int cur = t & 1;
        float* h1c = sh1 + cur * MTILE * S_H;
        float* h1n = sh1 + (cur ^ 1) * MTILE * S_H;
        float* h2c = sh2 + cur * MTILE * S_H;
        float* h2n = sh2 + (cur ^ 1) * MTILE * S_H;
        uint32_t a_h1c = u16_1 + cur * 16384;
        uint32_t a_h1n = u16_1 + (cur ^ 1) * 16384;
        uint32_t a_h2c = u16_2 + cur * 16384;
        uint32_t a_h2n = u16_2 + (cur ^ 1) * 16384;
        uint32_t a_x   = ux16 + cur * 4096;
        char* h1n16 = h16_1 + (cur ^ 1) * 16384;
        char* h2n16 = h16_2 + (cur ^ 1) * 16384;

        __syncthreads();   // x[cur] staged, previous-step writes visible

        // issue x_{t+1} loads early
        float4 vx0, vx1;
        if (tid < 256 && t + 1 < T_) {
            const float* xp = xbase + (size_t)(t + 1) * D_;
            vx0 = *reinterpret_cast<const float4*>(xp);
            vx1 = *reinterpret_cast<const float4*>(xp + 4);
        }

        // ---- Layer 1 (fused K=64+256 weight stream) ----
        zero4(aR, aZ, aNi, aNh);
        gemmL<2>(a_x, a_h1c, 7, bL1, lhi, sxr, aR, aZ, aNi, aNh);
        epilogue(aR, aZ, aNi, aNh, h1c, h1n, h1n16, sB1, w, g, tig);
        __syncthreads();

        // ---- Layer 2 (input = new h1; fused K=256+256) ----
        zero4(aR, aZ, aNi, aNh);
        gemmL<8>(a_h1n, a_h2c, 9, bL2, lhi, sxr, aR, aZ, aNi, aNh);
        epilogue(aR, aZ, aNi, aNh, h2c, h2n, h2n16, sB2, w, g, tig);
        __syncthreads();

        // ---- Head (warps 0-7): y_t = h2_new @ W_fc^T + b_fc ----
        if (w < 8) {
            float aF[2][4];
#pragma unroll
            for (int m = 0; m < 2; m++)
#pragma unroll
                for (int q = 0; q < 4; q++) aF[m][q] = 0.f;
            gemmH(a_h2n, bF, lhi, sxr, aF);
            int d0 = w * 8 + 2 * tig;
            float bs0 = sBf[d0], bs1 = sBf[d0 + 1];
#pragma unroll
            for (int m = 0; m < 2; m++) {
                int r0 = g + m * 16, r1 = g + 8 + m * 16;
                float2 v;
                v.x = aF[m][0] + bs0; v.y = aF[m][1] + bs1;
                *reinterpret_cast<float2*>(
                    out + ((size_t)(b0 + r0) * T_ + t) * D_ + d0) = v;
                v.x = aF[m][2] + bs0; v.y = aF[m][3] + bs1;
                *reinterpret_cast<float2*>(
                    out + ((size_t)(b0 + r1) * T_ + t) * D_ + d0) = v;
            }
        }

        // park x_{t+1} into the other fp16 x buffer
        if (tid < 256 && t + 1 < T_) {
            uint4 p;
            p.x = pkh(vx0.x, vx0.y); p.y = pkh(vx0.z, vx0.w);
            p.z = pkh(vx1.x, vx1.y); p.w = pkh(vx1.z, vx1.w);
            *reinterpret_cast<uint4*>(x16 + (cur ^ 1) * 4096 + xoff) = p;
        }
    }
    __syncthreads();

    // final states (t=255 wrote buffer 0)
    if (tid < 256) {
        size_t base = (size_t)B_ * T_ * D_;
        for (int i = 0; i < MTILE; i++) {
            out[base + (size_t)(b0 + i) * H_ + tid] = sh1[i * S_H + tid];
            out[base + (size_t)B_ * H_ + (size_t)(b0 + i) * H_ + tid] =
                sh2[i * S_H + tid];
        }
    }
}

// ---------------------------------------------------------------------------
extern "C" void kernel_launch(void* const* d_in, const int* in_sizes, int n_in,
                              void* d_out, int out_size) {
    (void)in_sizes; (void)n_in; (void)out_size;
    const float* x     = (const float*)d_in[0];
    const float* h1    = (const float*)d_in[1];
    const float* h2    = (const float*)d_in[2];
    const float* W_ih1 = (const float*)d_in[3];
    const float* W_hh1 = (const float*)d_in[4];
    const float* b_ih1 = (const float*)d_in[5];
    const float* b_hh1 = (const float*)d_in[6];
    const float* W_ih2 = (const float*)d_in[7];
    const float* W_hh2 = (const float*)d_in[8];
    const float* b_ih2 = (const float*)d_in[9];
    const float* b_hh2 = (const float*)d_in[10];
    const float* W_fc  = (const float*)d_in[11];
    const float* b_fc  = (const float*)d_in[12];
    float* out = (float*)d_out;

    repack_comb<<<120, 256>>>(W_ih1, W_hh1, 64, 0);
    repack_comb<<<192, 256>>>(W_ih2, W_hh2, 256, 1);
    repack_head<<<8, 256>>>(W_fc);

    const int smem_bytes =
        (2 * MTILE * S_H * 2 + 4 * H_ * 2 + 64) * (int)sizeof(float) +
        2 * 32 * 512 * 2 +   // fp16 h1, h2 (double buffered)
        2 * 32 * 128;        // fp16 x (double buffered)
    cudaFuncSetAttribute(gru_main, cudaFuncAttributeMaxDynamicSharedMemorySize,
                         smem_bytes);

    gru_main<<<NBLK, NTHR, smem_bytes>>>(x, h1, h2, b_ih1, b_hh1, b_ih2, b_hh2,
                                         b_fc, out);
}